// round 11
// baseline (speedup 1.0000x reference)
#include <cuda_runtime.h>

// PSRoIAlign: feat [B=4, C=784, H=80, W=80] f32, rois [N=512, 5] f32
// out [N, 16, 7, 7] f32. Channel of output element = r = co*49 + ph*7 + pw.
//
// R11: two-pass. Pass 1 (tiny) precomputes per-(roi,bin) geometry tables:
//   - x tables [N*7]: W[8] bilinear weight vector (masks + 1/4 folded),
//     window base xa + need_hi flag (each entry shared by 112 threads)
//   - y tables [N*7]: 4 row offsets (plane base b*784*6400 folded in) +
//     4 y-weights
// Pass 2 (main, one output/thread, 401K threads): index math + 5 table
// loads + 4-8 LDG.128 + dot8s. ~70 instrs/thread vs ~130, low reg pressure.

#define PH 7
#define PW 7
#define HH 80
#define WW 80
#define CC 784
#define PLANE (HH * WW)
#define MAXN 4096

__device__ float4 gWlo[MAXN * PH];
__device__ float4 gWhi[MAXN * PH];
__device__ int    gXA [MAXN * PH];   // xa | (need_hi << 16)
__device__ int4   gOff[MAXN * PH];   // planeBase + {y0,y1i}*WW for sy=0,1
__device__ float4 gWy [MAXN * PH];   // {wA0, wB0, wA1, wB1}

__global__ void precompute_kernel(const float* __restrict__ rois, int nEntries)
{
    int j = blockIdx.x * blockDim.x + threadIdx.x;
    if (j >= nEntries) return;
    int n = j / PH;
    int p = j - n * PH;                 // serves as pw for x-table, ph for y-table

    const float* roi = rois + n * 5;
    int   b   = (int)roi[0];
    float rx1 = roi[1] * (float)WW;
    float ry1 = roi[2] * (float)HH;
    float rx2 = roi[3] * (float)WW;
    float ry2 = roi[4] * (float)HH;

    float roi_h = fmaxf(ry2 - ry1, 0.1f);
    float roi_w = fmaxf(rx2 - rx1, 0.1f);
    float bin_h = roi_h * (1.0f / PH);
    float bin_w = roi_w * (1.0f / PW);

    // ---------- x geometry for pw = p ----------
    float xs0 = rx1 + (float)p * bin_w + 0.25f * bin_w;
    float xs1 = xs0 + 0.5f * bin_w;
    float mx0 = (xs0 >= -1.0f && xs0 <= (float)WW) ? 1.0f : 0.0f;
    float mx1 = (xs1 >= -1.0f && xs1 <= (float)WW) ? 1.0f : 0.0f;
    float xc0 = fminf(fmaxf(xs0, 0.0f), (float)(WW - 1));
    float xc1 = fminf(fmaxf(xs1, 0.0f), (float)(WW - 1));
    int x00 = (int)floorf(xc0);
    int x01 = (int)floorf(xc1);
    int x10 = min(x00 + 1, WW - 1);
    int x11 = min(x01 + 1, WW - 1);
    float lx0 = xc0 - (float)x00, hx0 = 1.0f - lx0;
    float lx1 = xc1 - (float)x01, hx1 = 1.0f - lx1;

    int xa  = x00 & ~3;
    int o00 = x00 - xa;
    int o01 = x10 - xa;
    int o10 = x01 - xa;
    int o11 = x11 - xa;
    int need_hi = (o11 > 3) ? 1 : 0;

    float c0 = 0.25f * mx0 * hx0, c1 = 0.25f * mx0 * lx0;
    float c2 = 0.25f * mx1 * hx1, c3 = 0.25f * mx1 * lx1;
    float W[8];
    #pragma unroll
    for (int k = 0; k < 8; ++k) {
        float w = (o00 == k) ? c0 : 0.0f;
        w += (o01 == k) ? c1 : 0.0f;
        w += (o10 == k) ? c2 : 0.0f;
        w += (o11 == k) ? c3 : 0.0f;
        W[k] = w;
    }
    gWlo[j] = make_float4(W[0], W[1], W[2], W[3]);
    gWhi[j] = make_float4(W[4], W[5], W[6], W[7]);
    gXA[j]  = xa | (need_hi << 16);

    // ---------- y geometry for ph = p ----------
    int planeBase = b * (CC * PLANE);
    float ybase = ry1 + (float)p * bin_h;
    int   offs[4];
    float wy[4];
    #pragma unroll
    for (int sy = 0; sy < 2; ++sy) {
        float ys = ybase + ((float)sy * 0.5f + 0.25f) * bin_h;
        float my = (ys >= -1.0f && ys <= (float)HH) ? 1.0f : 0.0f;
        float yc = fminf(fmaxf(ys, 0.0f), (float)(HH - 1));
        int y0  = (int)floorf(yc);
        int y1i = min(y0 + 1, HH - 1);
        float ly = yc - (float)y0;
        offs[sy * 2 + 0] = planeBase + y0  * WW;
        offs[sy * 2 + 1] = planeBase + y1i * WW;
        wy[sy * 2 + 0] = my * (1.0f - ly);
        wy[sy * 2 + 1] = my * ly;
    }
    gOff[j] = make_int4(offs[0], offs[1], offs[2], offs[3]);
    gWy[j]  = make_float4(wy[0], wy[1], wy[2], wy[3]);
}

__device__ __forceinline__ float dot8(float4 lo, float4 hi,
                                      float4 Wl, float4 Wh) {
    float s = lo.x * Wl.x;
    s = fmaf(lo.y, Wl.y, s);
    s = fmaf(lo.z, Wl.z, s);
    s = fmaf(lo.w, Wl.w, s);
    s = fmaf(hi.x, Wh.x, s);
    s = fmaf(hi.y, Wh.y, s);
    s = fmaf(hi.z, Wh.z, s);
    s = fmaf(hi.w, Wh.w, s);
    return s;
}

__global__ void __launch_bounds__(256, 6)
psroi_align_kernel(const float* __restrict__ feat,
                   float* __restrict__ out,
                   int total)
{
    int tid = blockIdx.x * blockDim.x + threadIdx.x;
    if (tid >= total) return;

    int n = tid / (PH * PW * 16);
    int r = tid - n * (PH * PW * 16);      // channel index
    int pw = r % PW;
    int ph = (r / PW) % PH;

    int jx = n * PH + pw;
    int jy = n * PH + ph;

    int xah = gXA[jx];
    int xa = xah & 0xFFFF;
    bool need_hi = (xah >> 16) != 0;
    float4 Wl = gWlo[jx];
    float4 Wh = gWhi[jx];
    int4   offs = gOff[jy];
    float4 wy   = gWy[jy];

    int cbase = r * PLANE + xa;            // channel plane + window base

    const float* pA0 = feat + (offs.x + cbase);
    const float* pB0 = feat + (offs.y + cbase);
    const float* pA1 = feat + (offs.z + cbase);
    const float* pB1 = feat + (offs.w + cbase);

    float4 zero = make_float4(0.f, 0.f, 0.f, 0.f);
    float acc;

    // round sy = 0
    {
        float4 Alo = __ldg((const float4*)pA0);
        float4 Blo = __ldg((const float4*)pB0);
        float4 Ahi = zero, Bhi = zero;
        if (need_hi) {
            Ahi = __ldg((const float4*)(pA0 + 4));
            Bhi = __ldg((const float4*)(pB0 + 4));
        }
        acc = wy.x * dot8(Alo, Ahi, Wl, Wh);
        acc = fmaf(wy.y, dot8(Blo, Bhi, Wl, Wh), acc);
    }
    // round sy = 1
    {
        float4 Alo = __ldg((const float4*)pA1);
        float4 Blo = __ldg((const float4*)pB1);
        float4 Ahi = zero, Bhi = zero;
        if (need_hi) {
            Ahi = __ldg((const float4*)(pA1 + 4));
            Bhi = __ldg((const float4*)(pB1 + 4));
        }
        acc = fmaf(wy.z, dot8(Alo, Ahi, Wl, Wh), acc);
        acc = fmaf(wy.w, dot8(Blo, Bhi, Wl, Wh), acc);
    }

    out[tid] = acc;
}

extern "C" void kernel_launch(void* const* d_in, const int* in_sizes, int n_in,
                              void* d_out, int out_size)
{
    const float* feat = (const float*)d_in[0];
    const float* rois = (const float*)d_in[1];
    float* out = (float*)d_out;

    int N = in_sizes[1] / 5;            // 512 rois
    if (N > MAXN) N = MAXN;
    int nEntries = N * PH;              // 3584 table entries

    precompute_kernel<<<(nEntries + 127) / 128, 128>>>(rois, nEntries);

    int total = N * 16 * PH * PW;       // 401408 outputs
    int threads = 256;
    int blocks = (total + threads - 1) / threads;
    psroi_align_kernel<<<blocks, threads>>>(feat, out, total);
}

// round 12
// speedup vs baseline: 1.1210x; 1.1210x over previous
#include <cuda_runtime.h>

// PSRoIAlign: feat [B=4, C=784, H=80, W=80] f32, rois [N=512, 5] f32
// out [N, 16, 7, 7] f32. Channel of output element = r = co*49 + ph*7 + pw.
//
// R12: latency-chain split. One thread per (output, sy) pair: each thread
// does ONE load->consume phase (2-4 LDG.128) instead of two, then lane pairs
// combine via shfl.bfly(1); even lane stores. 802K threads, same resident
// warps, ~55% critical path per warp. W-vector consume (masks + 0.25 folded).

#define PH 7
#define PW 7
#define HH 80
#define WW 80
#define CC 784

__device__ __forceinline__ float dot8(float4 lo, float4 hi, const float* W) {
    float s = lo.x * W[0];
    s = fmaf(lo.y, W[1], s);
    s = fmaf(lo.z, W[2], s);
    s = fmaf(lo.w, W[3], s);
    s = fmaf(hi.x, W[4], s);
    s = fmaf(hi.y, W[5], s);
    s = fmaf(hi.z, W[6], s);
    s = fmaf(hi.w, W[7], s);
    return s;
}

__global__ void __launch_bounds__(256, 6)
psroi_align_kernel(const float* __restrict__ feat,
                   const float* __restrict__ rois,
                   float* __restrict__ out,
                   int total2)   // = N * 784 * 2
{
    int tid = blockIdx.x * blockDim.x + threadIdx.x;
    if (tid >= total2) return;

    int p  = tid >> 1;                     // output element index
    int sy = tid & 1;                      // which y-sample this thread owns

    int n = p / (PH * PW * 16);
    int r = p - n * (PH * PW * 16);        // channel index
    int pw = r % PW;
    int ph = (r / PW) % PH;

    const float* roi = rois + n * 5;
    int   b   = (int)roi[0];
    float rx1 = roi[1] * (float)WW;
    float ry1 = roi[2] * (float)HH;
    float rx2 = roi[3] * (float)WW;
    float ry2 = roi[4] * (float)HH;

    float roi_h = fmaxf(ry2 - ry1, 0.1f);
    float roi_w = fmaxf(rx2 - rx1, 0.1f);
    float bin_h = roi_h * (1.0f / PH);
    float bin_w = roi_w * (1.0f / PW);

    const float* __restrict__ f = feat + ((size_t)b * CC + (size_t)r) * (HH * WW);

    // ---- x geometry (both sx samples; identical for the lane pair) ----
    float xs0 = rx1 + (float)pw * bin_w + 0.25f * bin_w;
    float xs1 = xs0 + 0.5f * bin_w;
    float mx0 = (xs0 >= -1.0f && xs0 <= (float)WW) ? 1.0f : 0.0f;
    float mx1 = (xs1 >= -1.0f && xs1 <= (float)WW) ? 1.0f : 0.0f;
    float xc0 = fminf(fmaxf(xs0, 0.0f), (float)(WW - 1));
    float xc1 = fminf(fmaxf(xs1, 0.0f), (float)(WW - 1));
    int x00 = (int)floorf(xc0);
    int x01 = (int)floorf(xc1);
    int x10 = min(x00 + 1, WW - 1);
    int x11 = min(x01 + 1, WW - 1);
    float lx0 = xc0 - (float)x00, hx0 = 1.0f - lx0;
    float lx1 = xc1 - (float)x01, hx1 = 1.0f - lx1;

    int xa  = x00 & ~3;
    int o00 = x00 - xa;                    // 0..3
    int o01 = x10 - xa;                    // 0..4
    int o10 = x01 - xa;                    // 0..5
    int o11 = x11 - xa;                    // 0..6
    bool need_hi = o11 > 3;                // implies xa <= 72; hi window in-bounds

    // ---- y geometry for this thread's sy only ----
    float ys = ry1 + (float)ph * bin_h + ((float)sy * 0.5f + 0.25f) * bin_h;
    float my = (ys >= -1.0f && ys <= (float)HH) ? 1.0f : 0.0f;
    float yc = fminf(fmaxf(ys, 0.0f), (float)(HH - 1));
    int y0  = (int)floorf(yc);
    int y1i = min(y0 + 1, HH - 1);
    float ly = yc - (float)y0;
    float hy = 1.0f - ly;

    const float* rowA = f + y0  * WW + xa;
    const float* rowB = f + y1i * WW + xa;

    // ---- issue this thread's loads (single memory phase) ----
    float4 Alo = __ldg((const float4*)rowA);
    float4 Blo = __ldg((const float4*)rowB);
    float4 Ahi = make_float4(0.f, 0.f, 0.f, 0.f);
    float4 Bhi = Ahi;
    if (need_hi) {
        Ahi = __ldg((const float4*)(rowA + 4));
        Bhi = __ldg((const float4*)(rowB + 4));
    }

    // ---- W vector while loads are in flight (masks + 1/4 folded) ----
    float c0 = 0.25f * mx0 * hx0, c1 = 0.25f * mx0 * lx0;
    float c2 = 0.25f * mx1 * hx1, c3 = 0.25f * mx1 * lx1;
    float W[8];
    #pragma unroll
    for (int k = 0; k < 8; ++k) {
        float w = (o00 == k) ? c0 : 0.0f;
        w += (o01 == k) ? c1 : 0.0f;
        w += (o10 == k) ? c2 : 0.0f;
        w += (o11 == k) ? c3 : 0.0f;
        W[k] = w;
    }

    float acc = my * (hy * dot8(Alo, Ahi, W) + ly * dot8(Blo, Bhi, W));

    // ---- combine lane pair (sy=0 with sy=1), even lane stores ----
    acc += __shfl_xor_sync(0xFFFFFFFFu, acc, 1);
    if (sy == 0) out[p] = acc;
}

extern "C" void kernel_launch(void* const* d_in, const int* in_sizes, int n_in,
                              void* d_out, int out_size)
{
    const float* feat = (const float*)d_in[0];
    const float* rois = (const float*)d_in[1];
    float* out = (float*)d_out;

    int N = in_sizes[1] / 5;            // 512 rois
    int total2 = N * 16 * PH * PW * 2;  // 802816 threads

    int threads = 256;
    int blocks = (total2 + threads - 1) / threads;
    psroi_align_kernel<<<blocks, threads>>>(feat, rois, out, total2);
}